// round 2
// baseline (speedup 1.0000x reference)
#include <cuda_runtime.h>

#define FULLMASK 0xffffffffu

static const int CH  = 64;
static const int HWX = 65536;   // 256*256
static const int WD  = 256;

// Scratch (device globals are the sanctioned scratch mechanism)
__device__ float g_q[16777216];   // [B*C][HW]
__device__ float g_v[16777216];   // [B*C][HW]
__device__ float g_k[67108864];   // [N*B*C][HW]
__device__ float g_ps[16777216];  // [B*C][W][W]  (sum over n of space softmax)

__device__ __forceinline__ float warp_max(float v) {
#pragma unroll
  for (int o = 16; o > 0; o >>= 1) v = fmaxf(v, __shfl_xor_sync(FULLMASK, v, o));
  return v;
}
__device__ __forceinline__ float warp_sum(float v) {
#pragma unroll
  for (int o = 16; o > 0; o >>= 1) v += __shfl_xor_sync(FULLMASK, v, o);
  return v;
}

// ---------------------------------------------------------------------------
// conv1x1: y[pb][oc][px] = sum_i w[oc][i] * x[pb][i][px] + b[oc]
// grid: (HW/64, P) ; 256 threads ; each thread: 4 oc x 4 px (x2 outputs if DUAL)
// ---------------------------------------------------------------------------
template <bool DUAL>
__global__ __launch_bounds__(256, 1) void conv1x1_kernel(
    const float* __restrict__ x,
    const float* __restrict__ w1, const float* __restrict__ b1, float* __restrict__ y1,
    const float* __restrict__ w2, const float* __restrict__ b2, float* __restrict__ y2)
{
  extern __shared__ float sm[];
  float* Xs  = sm;            // [64 i][64 px]
  float* W1s = sm + 4096;     // [64 oc][64 i]
  float* W2s = sm + 8192;     // [64 oc][64 i] (DUAL only)

  const int tid = threadIdx.x;
  const int pb  = blockIdx.y;
  const int px0 = blockIdx.x * 64;
  const float* xp = x + (size_t)pb * CH * HWX;

#pragma unroll 4
  for (int idx = tid; idx < 4096; idx += 256) {
    W1s[idx] = w1[idx];
    if (DUAL) W2s[idx] = w2[idx];
    Xs[idx] = xp[(size_t)(idx >> 6) * HWX + px0 + (idx & 63)];
  }
  __syncthreads();

  const int ocg = tid >> 4;   // 0..15
  const int pxg = tid & 15;   // 0..15
  float a1[4][4] = {};
  float a2[4][4] = {};

#pragma unroll 8
  for (int i = 0; i < 64; i++) {
    float4 xv = *(const float4*)&Xs[i * 64 + pxg * 4];
#pragma unroll
    for (int r = 0; r < 4; r++) {
      float wv = W1s[(ocg * 4 + r) * 64 + i];
      a1[r][0] += wv * xv.x; a1[r][1] += wv * xv.y;
      a1[r][2] += wv * xv.z; a1[r][3] += wv * xv.w;
      if (DUAL) {
        float w2v = W2s[(ocg * 4 + r) * 64 + i];
        a2[r][0] += w2v * xv.x; a2[r][1] += w2v * xv.y;
        a2[r][2] += w2v * xv.z; a2[r][3] += w2v * xv.w;
      }
    }
  }

#pragma unroll
  for (int r = 0; r < 4; r++) {
    int oc = ocg * 4 + r;
    size_t base = (size_t)pb * CH * HWX + (size_t)oc * HWX + px0 + pxg * 4;
    float bb = b1[oc];
    float4 o1 = make_float4(a1[r][0] + bb, a1[r][1] + bb, a1[r][2] + bb, a1[r][3] + bb);
    *(float4*)&y1[base] = o1;
    if (DUAL) {
      float bb2 = b2[oc];
      float4 o2 = make_float4(a2[r][0] + bb2, a2[r][1] + bb2, a2[r][2] + bb2, a2[r][3] + bb2);
      *(float4*)&y2[base] = o2;
    }
  }
}

// ---------------------------------------------------------------------------
// Fused time attention: per (bc, 64-row h block):
//   Pacc = sum_n rowsoftmax(Q_blk K_n^T / 16)   (softmax rows live in one warp)
//   out_blk = main_blk + Pacc @ V
// grid: (256, 4) ; 256 threads ; thread microtile 8x8
// smem: Qs[64][256] + KV[64][260] + Ps[64][256]  = 197632 B
// ---------------------------------------------------------------------------
__global__ __launch_bounds__(256, 1) void time_attn_kernel(
    const float* __restrict__ mainx, float* __restrict__ out)
{
  extern __shared__ float sm[];
  float* Qs = sm;              // 16384 floats  [64 h][256 w]
  float* KV = sm + 16384;      // 16640 floats  [64 w][260] (K^T tile) / [64 g][256 w] (V tile)
  float* Ps = sm + 33024;      // 16384 floats  [64 h][256 g]

  const int bc  = blockIdx.x;
  const int h0  = blockIdx.y * 64;
  const int tid = threadIdx.x;
  const int th  = tid >> 5;    // 0..7  (row group)
  const int tg  = tid & 31;    // 0..31 (col group)

  const float* qpl = g_q + (size_t)bc * HWX;
  const float* vpl = g_v + (size_t)bc * HWX;

  // Q block (contiguous rows)
#pragma unroll 4
  for (int idx = tid; idx < 16384; idx += 256) Qs[idx] = qpl[h0 * WD + idx];

  float Pacc[8][8];
#pragma unroll
  for (int r = 0; r < 8; r++)
#pragma unroll
    for (int j = 0; j < 8; j++) Pacc[r][j] = 0.f;

  const float scale = 0.0625f;  // 1/sqrt(256)

  for (int n = 0; n < 4; n++) {
    const float* kpl = g_k + ((size_t)n * 256 + bc) * HWX;
    float Sacc[8][8];
#pragma unroll
    for (int r = 0; r < 8; r++)
#pragma unroll
      for (int j = 0; j < 8; j++) Sacc[r][j] = 0.f;

    for (int wt = 0; wt < 4; wt++) {
      __syncthreads();
      const int w0 = wt * 64;
      // load K tile transposed: KV[w][g] = k[g][w0+w]
#pragma unroll 4
      for (int idx = tid; idx < 16384; idx += 256) {
        int g = idx >> 6, w = idx & 63;
        KV[w * 260 + g] = kpl[g * WD + w0 + w];
      }
      __syncthreads();
#pragma unroll 4
      for (int w = 0; w < 64; w++) {
        float qv[8];
#pragma unroll
        for (int r = 0; r < 8; r++) qv[r] = Qs[(th * 8 + r) * WD + w0 + w];
        float4 k0 = *(const float4*)&KV[w * 260 + tg * 8];
        float4 k1 = *(const float4*)&KV[w * 260 + tg * 8 + 4];
        float kv[8] = {k0.x, k0.y, k0.z, k0.w, k1.x, k1.y, k1.z, k1.w};
#pragma unroll
        for (int r = 0; r < 8; r++)
#pragma unroll
          for (int j = 0; j < 8; j++) Sacc[r][j] += qv[r] * kv[j];
      }
    }
    // per-row softmax across the warp (row h -> lanes tg, 8 vals/lane)
#pragma unroll
    for (int r = 0; r < 8; r++) {
      float m = -1e30f;
#pragma unroll
      for (int j = 0; j < 8; j++) { Sacc[r][j] *= scale; m = fmaxf(m, Sacc[r][j]); }
      m = warp_max(m);
      float l = 0.f;
#pragma unroll
      for (int j = 0; j < 8; j++) { Sacc[r][j] = __expf(Sacc[r][j] - m); l += Sacc[r][j]; }
      l = warp_sum(l);
      float inv = 1.0f / l;
#pragma unroll
      for (int j = 0; j < 8; j++) Pacc[r][j] += Sacc[r][j] * inv;
    }
  }

  // Pacc -> smem
#pragma unroll
  for (int r = 0; r < 8; r++) {
    *(float4*)&Ps[(th * 8 + r) * WD + tg * 8]     = make_float4(Pacc[r][0], Pacc[r][1], Pacc[r][2], Pacc[r][3]);
    *(float4*)&Ps[(th * 8 + r) * WD + tg * 8 + 4] = make_float4(Pacc[r][4], Pacc[r][5], Pacc[r][6], Pacc[r][7]);
  }

  // ctx: O = Pacc @ V
  float Oacc[8][8];
#pragma unroll
  for (int r = 0; r < 8; r++)
#pragma unroll
    for (int j = 0; j < 8; j++) Oacc[r][j] = 0.f;

  for (int gt = 0; gt < 4; gt++) {
    __syncthreads();
    const int g0 = gt * 64;
#pragma unroll 4
    for (int idx = tid; idx < 16384; idx += 256) KV[idx] = vpl[g0 * WD + idx];
    __syncthreads();
#pragma unroll 4
    for (int g = 0; g < 64; g++) {
      float pv[8];
#pragma unroll
      for (int r = 0; r < 8; r++) pv[r] = Ps[(th * 8 + r) * WD + g0 + g];
      float4 v0 = *(const float4*)&KV[g * WD + tg * 8];
      float4 v1 = *(const float4*)&KV[g * WD + tg * 8 + 4];
      float vv[8] = {v0.x, v0.y, v0.z, v0.w, v1.x, v1.y, v1.z, v1.w};
#pragma unroll
      for (int r = 0; r < 8; r++)
#pragma unroll
        for (int j = 0; j < 8; j++) Oacc[r][j] += pv[r] * vv[j];
    }
  }

  const float* mpl = mainx + (size_t)bc * HWX;
  float* opl = out + (size_t)bc * HWX;
#pragma unroll
  for (int r = 0; r < 8; r++) {
    int row = h0 + th * 8 + r;
    float4 m0 = *(const float4*)&mpl[row * WD + tg * 8];
    float4 m1 = *(const float4*)&mpl[row * WD + tg * 8 + 4];
    float4 o0 = make_float4(m0.x + Oacc[r][0], m0.y + Oacc[r][1], m0.z + Oacc[r][2], m0.w + Oacc[r][3]);
    float4 o1 = make_float4(m1.x + Oacc[r][4], m1.y + Oacc[r][5], m1.z + Oacc[r][6], m1.w + Oacc[r][7]);
    *(float4*)&opl[row * WD + tg * 8]     = o0;
    *(float4*)&opl[row * WD + tg * 8 + 4] = o1;
  }
}

// ---------------------------------------------------------------------------
// Space scores: g_ps[bc][w][v] = sum_n rowsoftmax_v( (Q^T K_n)[w][v] / 16 )
// grid: (256, 4 w-blocks) ; smem: Qt[256 h][64 w] + Kt[64 h][256 v] = 131072 B
// ---------------------------------------------------------------------------
__global__ __launch_bounds__(256, 1) void space_score_kernel()
{
  extern __shared__ float sm[];
  float* Qt = sm;           // [256 h][64 w]  (Q columns w0..w0+63)
  float* Kt = sm + 16384;   // [64 h][256 v]

  const int bc  = blockIdx.x;
  const int w0  = blockIdx.y * 64;
  const int tid = threadIdx.x;
  const int th  = tid >> 5;
  const int tg  = tid & 31;

  const float* qpl = g_q + (size_t)bc * HWX;
#pragma unroll 4
  for (int idx = tid; idx < 16384; idx += 256) {
    int h = idx >> 6, wl = idx & 63;
    Qt[idx] = qpl[h * WD + w0 + wl];
  }

  float Pacc[8][8];
#pragma unroll
  for (int r = 0; r < 8; r++)
#pragma unroll
    for (int j = 0; j < 8; j++) Pacc[r][j] = 0.f;

  const float scale = 0.0625f;

  for (int n = 0; n < 4; n++) {
    const float* kpl = g_k + ((size_t)n * 256 + bc) * HWX;
    float Sacc[8][8];
#pragma unroll
    for (int r = 0; r < 8; r++)
#pragma unroll
      for (int j = 0; j < 8; j++) Sacc[r][j] = 0.f;

    for (int ht = 0; ht < 4; ht++) {
      __syncthreads();
#pragma unroll 4
      for (int idx = tid; idx < 16384; idx += 256) Kt[idx] = kpl[(ht * 64) * WD + idx];
      __syncthreads();
#pragma unroll 4
      for (int hl = 0; hl < 64; hl++) {
        float qv[8];
#pragma unroll
        for (int r = 0; r < 8; r++) qv[r] = Qt[(ht * 64 + hl) * 64 + th * 8 + r];
        float4 k0 = *(const float4*)&Kt[hl * WD + tg * 8];
        float4 k1 = *(const float4*)&Kt[hl * WD + tg * 8 + 4];
        float kv[8] = {k0.x, k0.y, k0.z, k0.w, k1.x, k1.y, k1.z, k1.w};
#pragma unroll
        for (int r = 0; r < 8; r++)
#pragma unroll
          for (int j = 0; j < 8; j++) Sacc[r][j] += qv[r] * kv[j];
      }
    }
#pragma unroll
    for (int r = 0; r < 8; r++) {
      float m = -1e30f;
#pragma unroll
      for (int j = 0; j < 8; j++) { Sacc[r][j] *= scale; m = fmaxf(m, Sacc[r][j]); }
      m = warp_max(m);
      float l = 0.f;
#pragma unroll
      for (int j = 0; j < 8; j++) { Sacc[r][j] = __expf(Sacc[r][j] - m); l += Sacc[r][j]; }
      l = warp_sum(l);
      float inv = 1.0f / l;
#pragma unroll
      for (int j = 0; j < 8; j++) Pacc[r][j] += Sacc[r][j] * inv;
    }
  }

  float* ppl = g_ps + (size_t)bc * HWX;
#pragma unroll
  for (int r = 0; r < 8; r++) {
    int row = w0 + th * 8 + r;
    *(float4*)&ppl[row * WD + tg * 8]     = make_float4(Pacc[r][0], Pacc[r][1], Pacc[r][2], Pacc[r][3]);
    *(float4*)&ppl[row * WD + tg * 8 + 4] = make_float4(Pacc[r][4], Pacc[r][5], Pacc[r][6], Pacc[r][7]);
  }
}

// ---------------------------------------------------------------------------
// Space ctx: out[bc][h][v] += sum_w v[h][w] * g_ps[bc][w][v]
// grid: (256, 4 h-blocks) ; smem: Vt[64][256] + Pt[64][256] = 131072 B
// ---------------------------------------------------------------------------
__global__ __launch_bounds__(256, 1) void space_ctx_kernel(float* __restrict__ out)
{
  extern __shared__ float sm[];
  float* Vt = sm;           // [64 h][256 w]
  float* Pt = sm + 16384;   // [64 w][256 v]

  const int bc  = blockIdx.x;
  const int h0  = blockIdx.y * 64;
  const int tid = threadIdx.x;
  const int th  = tid >> 5;
  const int tg  = tid & 31;

  const float* vpl = g_v + (size_t)bc * HWX;
  const float* ppl = g_ps + (size_t)bc * HWX;

#pragma unroll 4
  for (int idx = tid; idx < 16384; idx += 256) Vt[idx] = vpl[h0 * WD + idx];

  float Oacc[8][8];
#pragma unroll
  for (int r = 0; r < 8; r++)
#pragma unroll
    for (int j = 0; j < 8; j++) Oacc[r][j] = 0.f;

  for (int wt = 0; wt < 4; wt++) {
    __syncthreads();
#pragma unroll 4
    for (int idx = tid; idx < 16384; idx += 256) Pt[idx] = ppl[(wt * 64) * WD + idx];
    __syncthreads();
#pragma unroll 4
    for (int wl = 0; wl < 64; wl++) {
      float vv[8];
#pragma unroll
      for (int r = 0; r < 8; r++) vv[r] = Vt[(th * 8 + r) * WD + wt * 64 + wl];
      float4 p0 = *(const float4*)&Pt[wl * WD + tg * 8];
      float4 p1 = *(const float4*)&Pt[wl * WD + tg * 8 + 4];
      float pv[8] = {p0.x, p0.y, p0.z, p0.w, p1.x, p1.y, p1.z, p1.w};
#pragma unroll
      for (int r = 0; r < 8; r++)
#pragma unroll
        for (int j = 0; j < 8; j++) Oacc[r][j] += vv[r] * pv[j];
    }
  }

  float* opl = out + (size_t)bc * HWX;
#pragma unroll
  for (int r = 0; r < 8; r++) {
    int row = h0 + th * 8 + r;
    float4 o0 = *(const float4*)&opl[row * WD + tg * 8];
    float4 o1 = *(const float4*)&opl[row * WD + tg * 8 + 4];
    o0.x += Oacc[r][0]; o0.y += Oacc[r][1]; o0.z += Oacc[r][2]; o0.w += Oacc[r][3];
    o1.x += Oacc[r][4]; o1.y += Oacc[r][5]; o1.z += Oacc[r][6]; o1.w += Oacc[r][7];
    *(float4*)&opl[row * WD + tg * 8]     = o0;
    *(float4*)&opl[row * WD + tg * 8 + 4] = o1;
  }
}

// ---------------------------------------------------------------------------
extern "C" void kernel_launch(void* const* d_in, const int* in_sizes, int n_in,
                              void* d_out, int out_size)
{
  (void)in_sizes; (void)n_in; (void)out_size;
  const float* mainx  = (const float*)d_in[0];
  const float* assist = (const float*)d_in[1];
  const float* wq = (const float*)d_in[2];
  const float* bq = (const float*)d_in[3];
  const float* wk = (const float*)d_in[4];
  const float* bk = (const float*)d_in[5];
  const float* wv = (const float*)d_in[6];
  const float* bv = (const float*)d_in[7];
  float* out = (float*)d_out;

  float *qp, *vp, *kp;
  cudaGetSymbolAddress((void**)&qp, g_q);
  cudaGetSymbolAddress((void**)&vp, g_v);
  cudaGetSymbolAddress((void**)&kp, g_k);

  cudaFuncSetAttribute(conv1x1_kernel<true>,  cudaFuncAttributeMaxDynamicSharedMemorySize, 49152);
  cudaFuncSetAttribute(conv1x1_kernel<false>, cudaFuncAttributeMaxDynamicSharedMemorySize, 32768);
  cudaFuncSetAttribute(time_attn_kernel,      cudaFuncAttributeMaxDynamicSharedMemorySize, 197632);
  cudaFuncSetAttribute(space_score_kernel,    cudaFuncAttributeMaxDynamicSharedMemorySize, 131072);
  cudaFuncSetAttribute(space_ctx_kernel,      cudaFuncAttributeMaxDynamicSharedMemorySize, 131072);

  // q, v from main (fused); k from assist
  conv1x1_kernel<true><<<dim3(1024, 4), 256, 49152>>>(mainx, wq, bq, qp, wv, bv, vp);
  conv1x1_kernel<false><<<dim3(1024, 16), 256, 32768>>>(assist, wk, bk, kp,
                                                        (const float*)0, (const float*)0, (float*)0);
  // out = main + (sum_n P_t,n) @ V
  time_attn_kernel<<<dim3(256, 4), 256, 197632>>>(mainx, out);
  // g_ps = sum_n P_s,n ; out += V @ g_ps
  space_score_kernel<<<dim3(256, 4), 256, 131072>>>();
  space_ctx_kernel<<<dim3(256, 4), 256, 131072>>>(out);
}

// round 5
// speedup vs baseline: 1.4907x; 1.4907x over previous
#include <cuda_runtime.h>
#include <cuda_bf16.h>
#include <cstdint>

static const int HWX = 65536;   // 256*256
static const int WD  = 256;
static const int CH  = 64;

// Scratch
__device__ float g_q[16777216];   // [B*C][HW]
__device__ float g_v[16777216];   // [B*C][HW]
__device__ float g_k[67108864];   // [N*B*C][HW]
__device__ float g_ps[16777216];  // [B*C][W][W]

// ---------------------------------------------------------------------------
// SMEM layout (bytes). Row pitch 144 B (72 bf16) -> conflict-free frag loads.
//   A: 4 chunks x [64 rows][64 k] bf16, hi + lo
//   B: 1 chunk  x [256 rows][64 k] bf16, hi + lo (streamed)
// ---------------------------------------------------------------------------
static const int PITCH   = 144;                   // bytes per row (72 bf16)
static const int A_CHUNK = 64 * PITCH;            // 9216
static const int B_CHUNK = 256 * PITCH;           // 36864
static const int SM_AH   = 0;
static const int SM_AL   = SM_AH + 4 * A_CHUNK;   // 36864
static const int SM_BH   = SM_AL + 4 * A_CHUNK;   // 73728
static const int SM_BL   = SM_BH + B_CHUNK;       // 110592
static const int SM_RS   = SM_BL + B_CHUNK;       // 147456 (rowsum: 2*64 floats)
static const int SM_TOTAL = SM_RS + 512;          // 147968

// split fp32 pair -> packed bf16x2 hi and lo (x0 in low 16 bits)
__device__ __forceinline__ void split2(float x0, float x1, uint32_t& hi2, uint32_t& lo2) {
  __nv_bfloat162 h = __floats2bfloat162_rn(x0, x1);
  float r0 = x0 - __bfloat162float(h.x);
  float r1 = x1 - __bfloat162float(h.y);
  __nv_bfloat162 l = __floats2bfloat162_rn(r0, r1);
  hi2 = *(uint32_t*)&h;
  lo2 = *(uint32_t*)&l;
}
__device__ __forceinline__ void split1(float x, __nv_bfloat16& h, __nv_bfloat16& l) {
  h = __float2bfloat16(x);
  l = __float2bfloat16(x - __bfloat162float(h));
}

__device__ __forceinline__ void mma16816(float c[4], uint32_t a0, uint32_t a1,
                                         uint32_t a2, uint32_t a3,
                                         uint32_t b0, uint32_t b1) {
  asm volatile(
    "mma.sync.aligned.m16n8k16.row.col.f32.bf16.bf16.f32 "
    "{%0,%1,%2,%3}, {%4,%5,%6,%7}, {%8,%9}, {%0,%1,%2,%3};"
    : "+f"(c[0]), "+f"(c[1]), "+f"(c[2]), "+f"(c[3])
    : "r"(a0), "r"(a1), "r"(a2), "r"(a3), "r"(b0), "r"(b1));
}

// ---------------------------------------------------------------------------
// Fill helpers (256 threads).
// ---------------------------------------------------------------------------
// A[m][k] = src[(m0+m)*256 + k]  (all 4 k-chunks at once)
__device__ __forceinline__ void fill_A_straight(char* smem, const float* src, int m0, int tid) {
  for (int idx = tid; idx < 4096; idx += 256) {
    int m = idx >> 6, q = idx & 63;
    int k = q * 4, chunk = k >> 6, kkb = (k & 63) * 2;
    float4 x = *(const float4*)(src + (size_t)(m0 + m) * WD + k);
    uint32_t h0, l0, h1, l1;
    split2(x.x, x.y, h0, l0);
    split2(x.z, x.w, h1, l1);
    char* ah = smem + SM_AH + chunk * A_CHUNK + m * PITCH + kkb;
    char* al = smem + SM_AL + chunk * A_CHUNK + m * PITCH + kkb;
    *(uint32_t*)ah = h0; *(uint32_t*)(ah + 4) = h1;
    *(uint32_t*)al = l0; *(uint32_t*)(al + 4) = l1;
  }
}

// A[m][k] = src[k*256 + w0 + m]  (transposed; all 4 k-chunks)
__device__ __forceinline__ void fill_A_trans(char* smem, const float* src, int w0, int tid) {
  for (int idx = tid; idx < 4096; idx += 256) {
    int k = idx >> 4, mg = idx & 15;
    int m = mg * 4, chunk = k >> 6, kkb = (k & 63) * 2;
    float4 x = *(const float4*)(src + (size_t)k * WD + w0 + m);
    char* ah = smem + SM_AH + chunk * A_CHUNK + kkb;
    char* al = smem + SM_AL + chunk * A_CHUNK + kkb;
#pragma unroll
    for (int j = 0; j < 4; j++) {
      __nv_bfloat16 h, l;
      split1((&x.x)[j], h, l);
      *(__nv_bfloat16*)(ah + (m + j) * PITCH) = h;
      *(__nv_bfloat16*)(al + (m + j) * PITCH) = l;
    }
  }
}

// B[n][kk] = src[n*256 + kc*64 + kk]
__device__ __forceinline__ void fill_B_straight(char* smem, const float* src, int kc, int tid) {
  for (int idx = tid; idx < 4096; idx += 256) {
    int n = idx >> 4, q = idx & 15;
    int kk = q * 4;
    float4 x = *(const float4*)(src + (size_t)n * WD + kc * 64 + kk);
    uint32_t h0, l0, h1, l1;
    split2(x.x, x.y, h0, l0);
    split2(x.z, x.w, h1, l1);
    char* bh = smem + SM_BH + n * PITCH + kk * 2;
    char* bl = smem + SM_BL + n * PITCH + kk * 2;
    *(uint32_t*)bh = h0; *(uint32_t*)(bh + 4) = h1;
    *(uint32_t*)bl = l0; *(uint32_t*)(bl + 4) = l1;
  }
}

// B[n][kk] = src[(kc*64+kk)*256 + n]  (transposed)
__device__ __forceinline__ void fill_B_trans(char* smem, const float* src, int kc, int tid) {
  for (int idx = tid; idx < 4096; idx += 256) {
    int kk = idx >> 6, ng = idx & 63;
    int n = ng * 4;
    float4 x = *(const float4*)(src + (size_t)(kc * 64 + kk) * WD + n);
    char* bh = smem + SM_BH + kk * 2;
    char* bl = smem + SM_BL + kk * 2;
#pragma unroll
    for (int j = 0; j < 4; j++) {
      __nv_bfloat16 h, l;
      split1((&x.x)[j], h, l);
      *(__nv_bfloat16*)(bh + (n + j) * PITCH) = h;
      *(__nv_bfloat16*)(bl + (n + j) * PITCH) = l;
    }
  }
}

// ---------------------------------------------------------------------------
// One 64-wide k-chunk of the warp-tile GEMM: acc[16][4] += A_chunk * B^T
// 3-term bf16 split. Warp computes rows 16*wm..+15, cols 128*wn + nt*8.
// NOTE: wm offset applies to A pointers ONLY (R3 bug: it leaked into B).
// ---------------------------------------------------------------------------
__device__ __forceinline__ void gemm_chunk(const char* smem, int kc, int lane,
                                           int wm, int wn, float acc[16][4]) {
  const int r = lane >> 2, t = lane & 3;
  const char* AH = smem + SM_AH + kc * A_CHUNK + wm * 16 * PITCH;
  const char* AL = smem + SM_AL + kc * A_CHUNK + wm * 16 * PITCH;
  const char* BH = smem + SM_BH;
  const char* BL = smem + SM_BL;
#pragma unroll
  for (int kt = 0; kt < 4; kt++) {
    const int kb = kt * 32 + t * 4;  // byte offset of this thread's k-pair
    uint32_t ah0 = *(const uint32_t*)(AH + (r)     * PITCH + kb);
    uint32_t ah1 = *(const uint32_t*)(AH + (r + 8) * PITCH + kb);
    uint32_t ah2 = *(const uint32_t*)(AH + (r)     * PITCH + kb + 16);
    uint32_t ah3 = *(const uint32_t*)(AH + (r + 8) * PITCH + kb + 16);
    uint32_t al0 = *(const uint32_t*)(AL + (r)     * PITCH + kb);
    uint32_t al1 = *(const uint32_t*)(AL + (r + 8) * PITCH + kb);
    uint32_t al2 = *(const uint32_t*)(AL + (r)     * PITCH + kb + 16);
    uint32_t al3 = *(const uint32_t*)(AL + (r + 8) * PITCH + kb + 16);
#pragma unroll
    for (int nt = 0; nt < 16; nt++) {
      const int n = wn * 128 + nt * 8 + r;
      uint32_t bh0 = *(const uint32_t*)(BH + n * PITCH + kb);
      uint32_t bh1 = *(const uint32_t*)(BH + n * PITCH + kb + 16);
      uint32_t bl0 = *(const uint32_t*)(BL + n * PITCH + kb);
      uint32_t bl1 = *(const uint32_t*)(BL + n * PITCH + kb + 16);
      mma16816(acc[nt], ah0, ah1, ah2, ah3, bh0, bh1);
      mma16816(acc[nt], al0, al1, al2, al3, bh0, bh1);
      mma16816(acc[nt], ah0, ah1, ah2, ah3, bl0, bl1);
    }
  }
}

// softmax over full 256-wide rows + accumulate into Pacc
__device__ __forceinline__ void softmax_acc(char* smem, float Sacc[16][4], float Pacc[16][4],
                                            int lane, int wm, int wn) {
  const int r = lane >> 2, t = lane & 3;
  float* rs = (float*)(smem + SM_RS);  // [2][64]
  float s0 = 0.f, s1 = 0.f;
#pragma unroll
  for (int nt = 0; nt < 16; nt++) {
#pragma unroll
    for (int e = 0; e < 4; e++) Sacc[nt][e] = __expf(Sacc[nt][e] * 0.0625f);
    s0 += Sacc[nt][0] + Sacc[nt][1];
    s1 += Sacc[nt][2] + Sacc[nt][3];
  }
#pragma unroll
  for (int o = 1; o <= 2; o <<= 1) {
    s0 += __shfl_xor_sync(0xffffffffu, s0, o);
    s1 += __shfl_xor_sync(0xffffffffu, s1, o);
  }
  if (t == 0) {
    rs[wn * 64 + wm * 16 + r]     = s0;
    rs[wn * 64 + wm * 16 + r + 8] = s1;
  }
  __syncthreads();
  float inv0 = 1.0f / (rs[wm * 16 + r]     + rs[64 + wm * 16 + r]);
  float inv1 = 1.0f / (rs[wm * 16 + r + 8] + rs[64 + wm * 16 + r + 8]);
#pragma unroll
  for (int nt = 0; nt < 16; nt++) {
    Pacc[nt][0] += Sacc[nt][0] * inv0;
    Pacc[nt][1] += Sacc[nt][1] * inv0;
    Pacc[nt][2] += Sacc[nt][2] * inv1;
    Pacc[nt][3] += Sacc[nt][3] * inv1;
  }
  __syncthreads();
}

// write Pacc fragments into the A-operand smem region (fragment-native layout)
__device__ __forceinline__ void store_P_to_A(char* smem, const float Pacc[16][4],
                                             int lane, int wm, int wn) {
  const int r = lane >> 2, t = lane & 3;
  const int m = wm * 16 + r;
#pragma unroll
  for (int nt = 0; nt < 16; nt++) {
    int chunk = wn * 2 + (nt >> 3);
    int kkb = ((nt & 7) * 8 + 2 * t) * 2;
    uint32_t hi, lo;
    split2(Pacc[nt][0], Pacc[nt][1], hi, lo);
    *(uint32_t*)(smem + SM_AH + chunk * A_CHUNK + m * PITCH + kkb) = hi;
    *(uint32_t*)(smem + SM_AL + chunk * A_CHUNK + m * PITCH + kkb) = lo;
    split2(Pacc[nt][2], Pacc[nt][3], hi, lo);
    *(uint32_t*)(smem + SM_AH + chunk * A_CHUNK + (m + 8) * PITCH + kkb) = hi;
    *(uint32_t*)(smem + SM_AL + chunk * A_CHUNK + (m + 8) * PITCH + kkb) = lo;
  }
}

// ---------------------------------------------------------------------------
// Kernel 3: time attention fused (scores + softmax-acc + P@V + out=main+O)
// grid (256 bc, 4 h-blocks of 64), 256 threads = warp grid 4(M) x 2(N)
// ---------------------------------------------------------------------------
__global__ __launch_bounds__(256, 1) void time_fused_kernel(
    const float* __restrict__ mainx, float* __restrict__ out)
{
  extern __shared__ char smem[];
  const int tid = threadIdx.x, lane = tid & 31, wid = tid >> 5;
  const int wm = wid & 3, wn = wid >> 2;
  const int bc = blockIdx.x, h0 = blockIdx.y * 64;

  const float* qp = g_q + (size_t)bc * HWX;
  const float* vp = g_v + (size_t)bc * HWX;

  fill_A_straight(smem, qp, h0, tid);

  float Pacc[16][4];
#pragma unroll
  for (int nt = 0; nt < 16; nt++)
#pragma unroll
    for (int e = 0; e < 4; e++) Pacc[nt][e] = 0.f;

  float Sacc[16][4];
  for (int n = 0; n < 4; n++) {
    const float* kp = g_k + ((size_t)n * 256 + bc) * HWX;
#pragma unroll
    for (int nt = 0; nt < 16; nt++)
#pragma unroll
      for (int e = 0; e < 4; e++) Sacc[nt][e] = 0.f;
    for (int kc = 0; kc < 4; kc++) {
      __syncthreads();
      fill_B_straight(smem, kp, kc, tid);
      __syncthreads();
      gemm_chunk(smem, kc, lane, wm, wn, Sacc);
    }
    softmax_acc(smem, Sacc, Pacc, lane, wm, wn);
  }

  __syncthreads();
  store_P_to_A(smem, Pacc, lane, wm, wn);

  // ctx: O = Pacc @ V   (reuse Sacc as Oacc)
#pragma unroll
  for (int nt = 0; nt < 16; nt++)
#pragma unroll
    for (int e = 0; e < 4; e++) Sacc[nt][e] = 0.f;
  for (int kc = 0; kc < 4; kc++) {
    __syncthreads();
    fill_B_trans(smem, vp, kc, tid);
    __syncthreads();
    gemm_chunk(smem, kc, lane, wm, wn, Sacc);
  }

  const float* mp = mainx + (size_t)bc * HWX;
  float* op = out + (size_t)bc * HWX;
  const int r = lane >> 2, t = lane & 3;
  const int row0 = h0 + wm * 16 + r;
#pragma unroll
  for (int nt = 0; nt < 16; nt++) {
    int col = wn * 128 + nt * 8 + 2 * t;
    float2 m0 = *(const float2*)&mp[(size_t)row0 * WD + col];
    float2 m1 = *(const float2*)&mp[(size_t)(row0 + 8) * WD + col];
    *(float2*)&op[(size_t)row0 * WD + col]       = make_float2(m0.x + Sacc[nt][0], m0.y + Sacc[nt][1]);
    *(float2*)&op[(size_t)(row0 + 8) * WD + col] = make_float2(m1.x + Sacc[nt][2], m1.y + Sacc[nt][3]);
  }
}

// ---------------------------------------------------------------------------
// Kernel 4: space scores: g_ps[w][v] = sum_n rowsoftmax_v((Q^T K_n)/16)
// ---------------------------------------------------------------------------
__global__ __launch_bounds__(256, 1) void space_score_kernel()
{
  extern __shared__ char smem[];
  const int tid = threadIdx.x, lane = tid & 31, wid = tid >> 5;
  const int wm = wid & 3, wn = wid >> 2;
  const int bc = blockIdx.x, w0 = blockIdx.y * 64;

  const float* qp = g_q + (size_t)bc * HWX;
  fill_A_trans(smem, qp, w0, tid);

  float Pacc[16][4];
#pragma unroll
  for (int nt = 0; nt < 16; nt++)
#pragma unroll
    for (int e = 0; e < 4; e++) Pacc[nt][e] = 0.f;

  float Sacc[16][4];
  for (int n = 0; n < 4; n++) {
    const float* kp = g_k + ((size_t)n * 256 + bc) * HWX;
#pragma unroll
    for (int nt = 0; nt < 16; nt++)
#pragma unroll
      for (int e = 0; e < 4; e++) Sacc[nt][e] = 0.f;
    for (int kc = 0; kc < 4; kc++) {
      __syncthreads();
      fill_B_trans(smem, kp, kc, tid);
      __syncthreads();
      gemm_chunk(smem, kc, lane, wm, wn, Sacc);
    }
    softmax_acc(smem, Sacc, Pacc, lane, wm, wn);
  }

  float* pp = g_ps + (size_t)bc * HWX;
  const int r = lane >> 2, t = lane & 3;
  const int row0 = w0 + wm * 16 + r;
#pragma unroll
  for (int nt = 0; nt < 16; nt++) {
    int col = wn * 128 + nt * 8 + 2 * t;
    *(float2*)&pp[(size_t)row0 * WD + col]       = make_float2(Pacc[nt][0], Pacc[nt][1]);
    *(float2*)&pp[(size_t)(row0 + 8) * WD + col] = make_float2(Pacc[nt][2], Pacc[nt][3]);
  }
}

// ---------------------------------------------------------------------------
// Kernel 5: space ctx: out[h][v] += sum_w v[h][w] * g_ps[w][v]
// ---------------------------------------------------------------------------
__global__ __launch_bounds__(256, 1) void space_ctx_kernel(float* __restrict__ out)
{
  extern __shared__ char smem[];
  const int tid = threadIdx.x, lane = tid & 31, wid = tid >> 5;
  const int wm = wid & 3, wn = wid >> 2;
  const int bc = blockIdx.x, h0 = blockIdx.y * 64;

  const float* vp = g_v + (size_t)bc * HWX;
  const float* pp = g_ps + (size_t)bc * HWX;
  fill_A_straight(smem, vp, h0, tid);

  float Oacc[16][4];
#pragma unroll
  for (int nt = 0; nt < 16; nt++)
#pragma unroll
    for (int e = 0; e < 4; e++) Oacc[nt][e] = 0.f;

  for (int kc = 0; kc < 4; kc++) {
    __syncthreads();
    fill_B_trans(smem, pp, kc, tid);
    __syncthreads();
    gemm_chunk(smem, kc, lane, wm, wn, Oacc);
  }

  float* op = out + (size_t)bc * HWX;
  const int r = lane >> 2, t = lane & 3;
  const int row0 = h0 + wm * 16 + r;
#pragma unroll
  for (int nt = 0; nt < 16; nt++) {
    int col = wn * 128 + nt * 8 + 2 * t;
    float2 o0 = *(const float2*)&op[(size_t)row0 * WD + col];
    float2 o1 = *(const float2*)&op[(size_t)(row0 + 8) * WD + col];
    *(float2*)&op[(size_t)row0 * WD + col]       = make_float2(o0.x + Oacc[nt][0], o0.y + Oacc[nt][1]);
    *(float2*)&op[(size_t)(row0 + 8) * WD + col] = make_float2(o1.x + Oacc[nt][2], o1.y + Oacc[nt][3]);
  }
}

// ---------------------------------------------------------------------------
// conv1x1 (unchanged from passing R1 kernel)
// ---------------------------------------------------------------------------
template <bool DUAL>
__global__ __launch_bounds__(256, 1) void conv1x1_kernel(
    const float* __restrict__ x,
    const float* __restrict__ w1, const float* __restrict__ b1, float* __restrict__ y1,
    const float* __restrict__ w2, const float* __restrict__ b2, float* __restrict__ y2)
{
  extern __shared__ float sm[];
  float* Xs  = sm;
  float* W1s = sm + 4096;
  float* W2s = sm + 8192;

  const int tid = threadIdx.x;
  const int pb  = blockIdx.y;
  const int px0 = blockIdx.x * 64;
  const float* xp = x + (size_t)pb * CH * HWX;

#pragma unroll 4
  for (int idx = tid; idx < 4096; idx += 256) {
    W1s[idx] = w1[idx];
    if (DUAL) W2s[idx] = w2[idx];
    Xs[idx] = xp[(size_t)(idx >> 6) * HWX + px0 + (idx & 63)];
  }
  __syncthreads();

  const int ocg = tid >> 4;
  const int pxg = tid & 15;
  float a1[4][4] = {};
  float a2[4][4] = {};

#pragma unroll 8
  for (int i = 0; i < 64; i++) {
    float4 xv = *(const float4*)&Xs[i * 64 + pxg * 4];
#pragma unroll
    for (int r = 0; r < 4; r++) {
      float wv = W1s[(ocg * 4 + r) * 64 + i];
      a1[r][0] += wv * xv.x; a1[r][1] += wv * xv.y;
      a1[r][2] += wv * xv.z; a1[r][3] += wv * xv.w;
      if (DUAL) {
        float w2v = W2s[(ocg * 4 + r) * 64 + i];
        a2[r][0] += w2v * xv.x; a2[r][1] += w2v * xv.y;
        a2[r][2] += w2v * xv.z; a2[r][3] += w2v * xv.w;
      }
    }
  }

#pragma unroll
  for (int r = 0; r < 4; r++) {
    int oc = ocg * 4 + r;
    size_t base = (size_t)pb * CH * HWX + (size_t)oc * HWX + px0 + pxg * 4;
    float bb = b1[oc];
    *(float4*)&y1[base] = make_float4(a1[r][0] + bb, a1[r][1] + bb, a1[r][2] + bb, a1[r][3] + bb);
    if (DUAL) {
      float bb2 = b2[oc];
      *(float4*)&y2[base] = make_float4(a2[r][0] + bb2, a2[r][1] + bb2, a2[r][2] + bb2, a2[r][3] + bb2);
    }
  }
}

// ---------------------------------------------------------------------------
extern "C" void kernel_launch(void* const* d_in, const int* in_sizes, int n_in,
                              void* d_out, int out_size)
{
  (void)in_sizes; (void)n_in; (void)out_size;
  const float* mainx  = (const float*)d_in[0];
  const float* assist = (const float*)d_in[1];
  const float* wq = (const float*)d_in[2];
  const float* bq = (const float*)d_in[3];
  const float* wk = (const float*)d_in[4];
  const float* bk = (const float*)d_in[5];
  const float* wv = (const float*)d_in[6];
  const float* bv = (const float*)d_in[7];
  float* out = (float*)d_out;

  float *qp, *vp, *kp;
  cudaGetSymbolAddress((void**)&qp, g_q);
  cudaGetSymbolAddress((void**)&vp, g_v);
  cudaGetSymbolAddress((void**)&kp, g_k);

  cudaFuncSetAttribute(conv1x1_kernel<true>,  cudaFuncAttributeMaxDynamicSharedMemorySize, 49152);
  cudaFuncSetAttribute(conv1x1_kernel<false>, cudaFuncAttributeMaxDynamicSharedMemorySize, 32768);
  cudaFuncSetAttribute(time_fused_kernel,  cudaFuncAttributeMaxDynamicSharedMemorySize, SM_TOTAL);
  cudaFuncSetAttribute(space_score_kernel, cudaFuncAttributeMaxDynamicSharedMemorySize, SM_TOTAL);
  cudaFuncSetAttribute(space_ctx_kernel,   cudaFuncAttributeMaxDynamicSharedMemorySize, SM_TOTAL);

  conv1x1_kernel<true><<<dim3(1024, 4), 256, 49152>>>(mainx, wq, bq, qp, wv, bv, vp);
  conv1x1_kernel<false><<<dim3(1024, 16), 256, 32768>>>(assist, wk, bk, kp,
                                                        (const float*)0, (const float*)0, (float*)0);
  time_fused_kernel<<<dim3(256, 4), 256, SM_TOTAL>>>(mainx, out);
  space_score_kernel<<<dim3(256, 4), 256, SM_TOTAL>>>();
  space_ctx_kernel<<<dim3(256, 4), 256, SM_TOTAL>>>(out);
}

// round 6
// speedup vs baseline: 3.0984x; 2.0785x over previous
#include <cuda_runtime.h>
#include <cuda_bf16.h>
#include <cstdint>

static const int HWX = 65536;   // 256*256
static const int WD  = 256;
static const int CH  = 64;

// ---------------------------------------------------------------------------
// Scratch: everything pre-split into bf16 hi/lo, straight and transposed.
// ---------------------------------------------------------------------------
__device__ __nv_bfloat16 g_qh[16777216],  g_ql[16777216];
__device__ __nv_bfloat16 g_vh[16777216],  g_vl[16777216];
__device__ __nv_bfloat16 g_kh[67108864],  g_kl[67108864];
__device__ __nv_bfloat16 g_qth[16777216], g_qtl[16777216];
__device__ __nv_bfloat16 g_vth[16777216], g_vtl[16777216];
__device__ __nv_bfloat16 g_kth[67108864], g_ktl[67108864];
__device__ __nv_bfloat16 g_psh[16777216], g_psl[16777216];  // sum_n P_space, TRANSPOSED [v][w]

// ---------------------------------------------------------------------------
// SMEM layout. PITCH 144 B per 64-k row -> conflict-free ldmatrix.
// A: 4 k-chunks x [64 rows] hi + lo. B: 2 buffers x ([256 rows] hi + lo).
// ---------------------------------------------------------------------------
static const int PITCH   = 144;
static const int A_CHUNK = 64 * PITCH;              // 9216
static const int SM_AH   = 0;                       // 4*9216 = 36864
static const int SM_AL   = 36864;                   // 36864
static const int B_PLANE = 256 * PITCH;             // 36864
static const int SM_B0H  = 73728;
static const int SM_B0L  = SM_B0H + B_PLANE;        // 110592
static const int SM_B1H  = SM_B0L + B_PLANE;        // 147456
static const int SM_B1L  = SM_B1H + B_PLANE;        // 184320
static const int SM_RS   = SM_B1L + B_PLANE;        // 221184 ([4][64] floats)
static const int SM_TOTAL = SM_RS + 1024;           // 222208

// ---------------------------------------------------------------------------
// Helpers
// ---------------------------------------------------------------------------
__device__ __forceinline__ uint32_t smem_u32(const void* p) {
  uint32_t a;
  asm("{ .reg .u64 t; cvta.to.shared.u64 t, %1; cvt.u32.u64 %0, t; }" : "=r"(a) : "l"(p));
  return a;
}
__device__ __forceinline__ void split2(float x0, float x1, uint32_t& hi2, uint32_t& lo2) {
  __nv_bfloat162 h = __floats2bfloat162_rn(x0, x1);
  float r0 = x0 - __bfloat162float(h.x);
  float r1 = x1 - __bfloat162float(h.y);
  __nv_bfloat162 l = __floats2bfloat162_rn(r0, r1);
  hi2 = *(uint32_t*)&h;
  lo2 = *(uint32_t*)&l;
}
__device__ __forceinline__ void split1(float x, __nv_bfloat16& h, __nv_bfloat16& l) {
  h = __float2bfloat16(x);
  l = __float2bfloat16(x - __bfloat162float(h));
}

__device__ __forceinline__ void mma16816(float c[4], uint32_t a0, uint32_t a1,
                                         uint32_t a2, uint32_t a3,
                                         uint32_t b0, uint32_t b1) {
  asm volatile(
    "mma.sync.aligned.m16n8k16.row.col.f32.bf16.bf16.f32 "
    "{%0,%1,%2,%3}, {%4,%5,%6,%7}, {%8,%9}, {%0,%1,%2,%3};"
    : "+f"(c[0]), "+f"(c[1]), "+f"(c[2]), "+f"(c[3])
    : "r"(a0), "r"(a1), "r"(a2), "r"(a3), "r"(b0), "r"(b1));
}
__device__ __forceinline__ void ldmx4(uint32_t& r0, uint32_t& r1, uint32_t& r2, uint32_t& r3,
                                      uint32_t addr) {
  asm volatile("ldmatrix.sync.aligned.m8n8.x4.shared.b16 {%0,%1,%2,%3}, [%4];"
               : "=r"(r0), "=r"(r1), "=r"(r2), "=r"(r3) : "r"(addr));
}

#define CP16(dst, src)  asm volatile("cp.async.cg.shared.global [%0], [%1], 16;" :: "r"(dst), "l"(src))
#define CP_COMMIT()     asm volatile("cp.async.commit_group;" ::: "memory")
#define CP_WAIT1()      asm volatile("cp.async.wait_group 1;" ::: "memory")
#define CP_WAIT0()      asm volatile("cp.async.wait_group 0;" ::: "memory")

// A fill (all 4 k-chunks, 64 rows): pure async copy from pre-split bf16.
__device__ __forceinline__ void cpa_A(uint32_t sb, const __nv_bfloat16* srcH,
                                      const __nv_bfloat16* srcL, size_t rowbase, int tid) {
  for (int idx = tid; idx < 4096; idx += 256) {
    int plane = idx >> 11, rem = idx & 2047;
    int m = rem >> 5, s = rem & 31;   // s = chunk*8 + 16B slot
    const __nv_bfloat16* src = (plane ? srcL : srcH) + rowbase + (size_t)m * WD + s * 8;
    uint32_t dst = sb + (plane ? SM_AL : SM_AH) + (s >> 3) * A_CHUNK + m * PITCH + (s & 7) * 16;
    CP16(dst, src);
  }
}
// B fill (one 64-k chunk, 256 rows)
__device__ __forceinline__ void cpa_B(uint32_t sb, uint32_t dH, uint32_t dL,
                                      const __nv_bfloat16* srcH, const __nv_bfloat16* srcL,
                                      size_t base, int koff, int tid) {
  for (int idx = tid; idx < 4096; idx += 256) {
    int plane = idx >> 11, rem = idx & 2047;
    int n = rem >> 3, s = rem & 7;
    const __nv_bfloat16* src = (plane ? srcL : srcH) + base + (size_t)n * WD + koff + s * 8;
    uint32_t dst = sb + (plane ? dL : dH) + n * PITCH + s * 16;
    CP16(dst, src);
  }
}

// ---------------------------------------------------------------------------
// One 64-k chunk: acc[2][8][4] += A_chunk * B^T  (3-term bf16 split)
// Warp tile 32(M) x 64(N): wm in {0,1}, wn in {0..3}.
// ---------------------------------------------------------------------------
__device__ __forceinline__ void gemm_chunk(uint32_t sb, int ac, uint32_t bufH, uint32_t bufL,
                                           int lane, int wm, int wn, float (&acc)[2][8][4]) {
  const int i8 = lane & 7, q = lane >> 3;
  uint32_t bAddr = sb + (q < 2 ? bufH : bufL) + (uint32_t)(wn * 64 + i8) * PITCH + (q & 1) * 16;
  const int i16 = lane & 15, hsel = lane >> 4;
  uint32_t aAddrH = sb + SM_AH + ac * A_CHUNK + (uint32_t)(wm * 32 + i16) * PITCH + hsel * 16;
  uint32_t aAddrL = aAddrH + (SM_AL - SM_AH);
#pragma unroll
  for (int kt = 0; kt < 4; kt++) {
    uint32_t h00, h01, h02, h03, h10, h11, h12, h13;
    uint32_t l00, l01, l02, l03, l10, l11, l12, l13;
    ldmx4(h00, h01, h02, h03, aAddrH + kt * 32);
    ldmx4(h10, h11, h12, h13, aAddrH + 16 * PITCH + kt * 32);
    ldmx4(l00, l01, l02, l03, aAddrL + kt * 32);
    ldmx4(l10, l11, l12, l13, aAddrL + 16 * PITCH + kt * 32);
#pragma unroll
    for (int nt = 0; nt < 8; nt++) {
      uint32_t b0, b1, b2, b3;  // bh0, bh1, bl0, bl1 in ONE ldmatrix
      ldmx4(b0, b1, b2, b3, bAddr + nt * 8 * PITCH + kt * 32);
      mma16816(acc[0][nt], h00, h01, h02, h03, b0, b1);
      mma16816(acc[1][nt], h10, h11, h12, h13, b0, b1);
      mma16816(acc[0][nt], l00, l01, l02, l03, b0, b1);
      mma16816(acc[1][nt], l10, l11, l12, l13, b0, b1);
      mma16816(acc[0][nt], h00, h01, h02, h03, b2, b3);
      mma16816(acc[1][nt], h10, h11, h12, h13, b2, b3);
    }
  }
}

__device__ __forceinline__ void zero_acc(float (&a)[2][8][4]) {
#pragma unroll
  for (int mi = 0; mi < 2; mi++)
#pragma unroll
    for (int nt = 0; nt < 8; nt++)
#pragma unroll
      for (int e = 0; e < 4; e++) a[mi][nt][e] = 0.f;
}

// softmax over full 256-wide rows (cols span the 4 wn warps), accumulate into P
__device__ __forceinline__ void softmax_acc(char* smem, float (&S)[2][8][4], float (&P)[2][8][4],
                                            int lane, int wm, int wn) {
  const int r = lane >> 2, t = lane & 3;
  float* rs = (float*)(smem + SM_RS);  // [4 wn][64 rows]
  float s[4] = {0.f, 0.f, 0.f, 0.f};
#pragma unroll
  for (int mi = 0; mi < 2; mi++)
#pragma unroll
    for (int nt = 0; nt < 8; nt++) {
#pragma unroll
      for (int e = 0; e < 4; e++) S[mi][nt][e] = __expf(S[mi][nt][e] * 0.0625f);
      s[mi * 2 + 0] += S[mi][nt][0] + S[mi][nt][1];
      s[mi * 2 + 1] += S[mi][nt][2] + S[mi][nt][3];
    }
#pragma unroll
  for (int o = 1; o <= 2; o <<= 1)
#pragma unroll
    for (int i = 0; i < 4; i++) s[i] += __shfl_xor_sync(0xffffffffu, s[i], o);
  if (t == 0) {
#pragma unroll
    for (int mi = 0; mi < 2; mi++) {
      rs[wn * 64 + wm * 32 + mi * 16 + r]     = s[mi * 2 + 0];
      rs[wn * 64 + wm * 32 + mi * 16 + r + 8] = s[mi * 2 + 1];
    }
  }
  __syncthreads();
#pragma unroll
  for (int mi = 0; mi < 2; mi++) {
    int row = wm * 32 + mi * 16 + r;
    float inv0 = 1.0f / (rs[row] + rs[64 + row] + rs[128 + row] + rs[192 + row]);
    float inv1 = 1.0f / (rs[row + 8] + rs[64 + row + 8] + rs[128 + row + 8] + rs[192 + row + 8]);
#pragma unroll
    for (int nt = 0; nt < 8; nt++) {
      P[mi][nt][0] += S[mi][nt][0] * inv0;
      P[mi][nt][1] += S[mi][nt][1] * inv0;
      P[mi][nt][2] += S[mi][nt][2] * inv1;
      P[mi][nt][3] += S[mi][nt][3] * inv1;
    }
  }
  __syncthreads();
}

// write P fragments into the A smem region (split, fragment-native layout)
__device__ __forceinline__ void store_P_to_A(char* smem, const float (&P)[2][8][4],
                                             int lane, int wm, int wn) {
  const int r = lane >> 2, t = lane & 3;
#pragma unroll
  for (int mi = 0; mi < 2; mi++)
#pragma unroll
    for (int nt = 0; nt < 8; nt++) {
      int m = wm * 32 + mi * 16 + r;
      int kk = (nt * 8 + 2 * t) * 2;  // byte offset within chunk row
      uint32_t hi, lo;
      split2(P[mi][nt][0], P[mi][nt][1], hi, lo);
      *(uint32_t*)(smem + SM_AH + wn * A_CHUNK + m * PITCH + kk) = hi;
      *(uint32_t*)(smem + SM_AL + wn * A_CHUNK + m * PITCH + kk) = lo;
      split2(P[mi][nt][2], P[mi][nt][3], hi, lo);
      *(uint32_t*)(smem + SM_AH + wn * A_CHUNK + (m + 8) * PITCH + kk) = hi;
      *(uint32_t*)(smem + SM_AL + wn * A_CHUNK + (m + 8) * PITCH + kk) = lo;
    }
}

// ---------------------------------------------------------------------------
// Kernel: time attention fused. grid (256 bc, 4 h-blocks). 8 warps = 2x4.
// ---------------------------------------------------------------------------
__global__ __launch_bounds__(256, 1) void time_fused_kernel(
    const float* __restrict__ mainx, float* __restrict__ out)
{
  extern __shared__ char smem[];
  uint32_t sb = smem_u32(smem);
  const int tid = threadIdx.x, lane = tid & 31, wid = tid >> 5;
  const int wm = wid & 1, wn = wid >> 1;
  const int bc = blockIdx.x, h0 = blockIdx.y * 64;
  const size_t pb = (size_t)bc * HWX;

  float Pacc[2][8][4], Sacc[2][8][4];
  zero_acc(Pacc);

  // A <- Q straight; prefetch first K chunk
  cpa_A(sb, g_qh, g_ql, pb + (size_t)h0 * WD, tid);
  cpa_B(sb, SM_B0H, SM_B0L, g_kh + pb, g_kl + pb, 0, 0, tid);
  CP_COMMIT();

  for (int c = 0; c < 16; c++) {
    int kc = c & 3;
    if (c + 1 < 16) {
      size_t b1 = ((size_t)((c + 1) >> 2) * 256 + bc) * HWX;
      uint32_t dh = ((c + 1) & 1) ? SM_B1H : SM_B0H;
      uint32_t dl = ((c + 1) & 1) ? SM_B1L : SM_B0L;
      cpa_B(sb, dh, dl, g_kh, g_kl, b1, ((c + 1) & 3) * 64, tid);
      CP_COMMIT();
      CP_WAIT1();
    } else {
      CP_WAIT0();
    }
    __syncthreads();
    if (kc == 0) zero_acc(Sacc);
    gemm_chunk(sb, kc, (c & 1) ? SM_B1H : SM_B0H, (c & 1) ? SM_B1L : SM_B0L, lane, wm, wn, Sacc);
    if (kc == 3) softmax_acc(smem, Sacc, Pacc, lane, wm, wn);
    else __syncthreads();
  }

  // ctx: A <- split(Pacc)
  store_P_to_A(smem, Pacc, lane, wm, wn);
  __syncthreads();
  zero_acc(Sacc);
  cpa_B(sb, SM_B0H, SM_B0L, g_vth + pb, g_vtl + pb, 0, 0, tid);
  CP_COMMIT();
  for (int kc = 0; kc < 4; kc++) {
    if (kc + 1 < 4) {
      uint32_t dh = ((kc + 1) & 1) ? SM_B1H : SM_B0H;
      uint32_t dl = ((kc + 1) & 1) ? SM_B1L : SM_B0L;
      cpa_B(sb, dh, dl, g_vth + pb, g_vtl + pb, 0, (kc + 1) * 64, tid);
      CP_COMMIT();
      CP_WAIT1();
    } else {
      CP_WAIT0();
    }
    __syncthreads();
    gemm_chunk(sb, kc, (kc & 1) ? SM_B1H : SM_B0H, (kc & 1) ? SM_B1L : SM_B0L, lane, wm, wn, Sacc);
    __syncthreads();
  }

  const float* mp = mainx + pb;
  float* op = out + pb;
  const int r = lane >> 2, t = lane & 3;
#pragma unroll
  for (int mi = 0; mi < 2; mi++)
#pragma unroll
    for (int nt = 0; nt < 8; nt++) {
      int row = h0 + wm * 32 + mi * 16 + r;
      int col = wn * 64 + nt * 8 + 2 * t;
      float2 m0 = *(const float2*)&mp[(size_t)row * WD + col];
      float2 m1 = *(const float2*)&mp[(size_t)(row + 8) * WD + col];
      *(float2*)&op[(size_t)row * WD + col]       = make_float2(m0.x + Sacc[mi][nt][0], m0.y + Sacc[mi][nt][1]);
      *(float2*)&op[(size_t)(row + 8) * WD + col] = make_float2(m1.x + Sacc[mi][nt][2], m1.y + Sacc[mi][nt][3]);
    }
}

// ---------------------------------------------------------------------------
// Kernel: space scores -> psT (transposed, split)
// ---------------------------------------------------------------------------
__global__ __launch_bounds__(256, 1) void space_score_kernel()
{
  extern __shared__ char smem[];
  uint32_t sb = smem_u32(smem);
  const int tid = threadIdx.x, lane = tid & 31, wid = tid >> 5;
  const int wm = wid & 1, wn = wid >> 1;
  const int bc = blockIdx.x, w0 = blockIdx.y * 64;
  const size_t pb = (size_t)bc * HWX;

  float Pacc[2][8][4], Sacc[2][8][4];
  zero_acc(Pacc);

  cpa_A(sb, g_qth, g_qtl, pb + (size_t)w0 * WD, tid);   // A = Q^T rows w
  cpa_B(sb, SM_B0H, SM_B0L, g_kth + pb, g_ktl + pb, 0, 0, tid);
  CP_COMMIT();

  for (int c = 0; c < 16; c++) {
    int kc = c & 3;
    if (c + 1 < 16) {
      size_t b1 = ((size_t)((c + 1) >> 2) * 256 + bc) * HWX;
      uint32_t dh = ((c + 1) & 1) ? SM_B1H : SM_B0H;
      uint32_t dl = ((c + 1) & 1) ? SM_B1L : SM_B0L;
      cpa_B(sb, dh, dl, g_kth, g_ktl, b1, ((c + 1) & 3) * 64, tid);
      CP_COMMIT();
      CP_WAIT1();
    } else {
      CP_WAIT0();
    }
    __syncthreads();
    if (kc == 0) zero_acc(Sacc);
    gemm_chunk(sb, kc, (c & 1) ? SM_B1H : SM_B0H, (c & 1) ? SM_B1L : SM_B0L, lane, wm, wn, Sacc);
    if (kc == 3) softmax_acc(smem, Sacc, Pacc, lane, wm, wn);
    else __syncthreads();
  }

  // write psT[v][w] (split) — scattered 2B stores
  const int r = lane >> 2, t = lane & 3;
#pragma unroll
  for (int mi = 0; mi < 2; mi++)
#pragma unroll
    for (int nt = 0; nt < 8; nt++) {
      int w = w0 + wm * 32 + mi * 16 + r;
      int v = wn * 64 + nt * 8 + 2 * t;
      __nv_bfloat16 h, l;
      split1(Pacc[mi][nt][0], h, l);
      g_psh[pb + (size_t)v * WD + w] = h;       g_psl[pb + (size_t)v * WD + w] = l;
      split1(Pacc[mi][nt][1], h, l);
      g_psh[pb + (size_t)(v + 1) * WD + w] = h; g_psl[pb + (size_t)(v + 1) * WD + w] = l;
      split1(Pacc[mi][nt][2], h, l);
      g_psh[pb + (size_t)v * WD + w + 8] = h;   g_psl[pb + (size_t)v * WD + w + 8] = l;
      split1(Pacc[mi][nt][3], h, l);
      g_psh[pb + (size_t)(v + 1) * WD + w + 8] = h; g_psl[pb + (size_t)(v + 1) * WD + w + 8] = l;
    }
}

// ---------------------------------------------------------------------------
// Kernel: space ctx: out[h][v] += sum_w v[h][w] * ps[w][v]
// ---------------------------------------------------------------------------
__global__ __launch_bounds__(256, 1) void space_ctx_kernel(float* __restrict__ out)
{
  extern __shared__ char smem[];
  uint32_t sb = smem_u32(smem);
  const int tid = threadIdx.x, lane = tid & 31, wid = tid >> 5;
  const int wm = wid & 1, wn = wid >> 1;
  const int bc = blockIdx.x, h0 = blockIdx.y * 64;
  const size_t pb = (size_t)bc * HWX;

  float Oacc[2][8][4];
  zero_acc(Oacc);

  cpa_A(sb, g_vh, g_vl, pb + (size_t)h0 * WD, tid);   // A = V straight
  cpa_B(sb, SM_B0H, SM_B0L, g_psh + pb, g_psl + pb, 0, 0, tid);
  CP_COMMIT();
  for (int kc = 0; kc < 4; kc++) {
    if (kc + 1 < 4) {
      uint32_t dh = ((kc + 1) & 1) ? SM_B1H : SM_B0H;
      uint32_t dl = ((kc + 1) & 1) ? SM_B1L : SM_B0L;
      cpa_B(sb, dh, dl, g_psh + pb, g_psl + pb, 0, (kc + 1) * 64, tid);
      CP_COMMIT();
      CP_WAIT1();
    } else {
      CP_WAIT0();
    }
    __syncthreads();
    gemm_chunk(sb, kc, (kc & 1) ? SM_B1H : SM_B0H, (kc & 1) ? SM_B1L : SM_B0L, lane, wm, wn, Oacc);
    __syncthreads();
  }

  float* op = out + pb;
  const int r = lane >> 2, t = lane & 3;
#pragma unroll
  for (int mi = 0; mi < 2; mi++)
#pragma unroll
    for (int nt = 0; nt < 8; nt++) {
      int row = h0 + wm * 32 + mi * 16 + r;
      int col = wn * 64 + nt * 8 + 2 * t;
      float2 o0 = *(const float2*)&op[(size_t)row * WD + col];
      float2 o1 = *(const float2*)&op[(size_t)(row + 8) * WD + col];
      *(float2*)&op[(size_t)row * WD + col]       = make_float2(o0.x + Oacc[mi][nt][0], o0.y + Oacc[mi][nt][1]);
      *(float2*)&op[(size_t)(row + 8) * WD + col] = make_float2(o1.x + Oacc[mi][nt][2], o1.y + Oacc[mi][nt][3]);
    }
}

// ---------------------------------------------------------------------------
// conv1x1 -> bf16 hi/lo outputs (x1 or x2)
// ---------------------------------------------------------------------------
template <bool DUAL>
__global__ __launch_bounds__(256, 1) void conv1x1_kernel(
    const float* __restrict__ x,
    const float* __restrict__ w1, const float* __restrict__ b1,
    __nv_bfloat16* __restrict__ y1h, __nv_bfloat16* __restrict__ y1l,
    const float* __restrict__ w2, const float* __restrict__ b2,
    __nv_bfloat16* __restrict__ y2h, __nv_bfloat16* __restrict__ y2l)
{
  extern __shared__ float sm[];
  float* Xs  = sm;
  float* W1s = sm + 4096;
  float* W2s = sm + 8192;

  const int tid = threadIdx.x;
  const int pb  = blockIdx.y;
  const int px0 = blockIdx.x * 64;
  const float* xp = x + (size_t)pb * CH * HWX;

#pragma unroll 4
  for (int idx = tid; idx < 4096; idx += 256) {
    W1s[idx] = w1[idx];
    if (DUAL) W2s[idx] = w2[idx];
    Xs[idx] = xp[(size_t)(idx >> 6) * HWX + px0 + (idx & 63)];
  }
  __syncthreads();

  const int ocg = tid >> 4;
  const int pxg = tid & 15;
  float a1[4][4] = {};
  float a2[4][4] = {};

#pragma unroll 8
  for (int i = 0; i < 64; i++) {
    float4 xv = *(const float4*)&Xs[i * 64 + pxg * 4];
#pragma unroll
    for (int r = 0; r < 4; r++) {
      float wv = W1s[(ocg * 4 + r) * 64 + i];
      a1[r][0] += wv * xv.x; a1[r][1] += wv * xv.y;
      a1[r][2] += wv * xv.z; a1[r][3] += wv * xv.w;
      if (DUAL) {
        float w2v = W2s[(ocg * 4 + r) * 64 + i];
        a2[r][0] += w2v * xv.x; a2[r][1] += w2v * xv.y;
        a2[r][2] += w2v * xv.z; a2[r][3] += w2v * xv.w;
      }
    }
  }

#pragma unroll
  for (int r = 0; r < 4; r++) {
    int oc = ocg * 4 + r;
    size_t base = (size_t)pb * CH * HWX + (size_t)oc * HWX + px0 + pxg * 4;
    float bb = b1[oc];
    uint32_t h0, l0, h1, l1;
    split2(a1[r][0] + bb, a1[r][1] + bb, h0, l0);
    split2(a1[r][2] + bb, a1[r][3] + bb, h1, l1);
    *(uint2*)(y1h + base) = make_uint2(h0, h1);
    *(uint2*)(y1l + base) = make_uint2(l0, l1);
    if (DUAL) {
      float bb2 = b2[oc];
      split2(a2[r][0] + bb2, a2[r][1] + bb2, h0, l0);
      split2(a2[r][2] + bb2, a2[r][3] + bb2, h1, l1);
      *(uint2*)(y2h + base) = make_uint2(h0, h1);
      *(uint2*)(y2l + base) = make_uint2(l0, l1);
    }
  }
}

// ---------------------------------------------------------------------------
// transpose bf16 hi/lo planes: dst[p][w*256+h] = src[p][h*256+w]
// grid: (planes, 16 tiles of 64x64), 256 threads
// ---------------------------------------------------------------------------
__global__ __launch_bounds__(256, 1) void transpose_kernel(
    const __nv_bfloat16* __restrict__ srcH, const __nv_bfloat16* __restrict__ srcL,
    __nv_bfloat16* __restrict__ dstH, __nv_bfloat16* __restrict__ dstL)
{
  __shared__ __nv_bfloat16 tile[2][64][72];
  const int p = blockIdx.x, tIdx = blockIdx.y;
  const int h0 = (tIdx >> 2) * 64, w0 = (tIdx & 3) * 64;
  const size_t base = (size_t)p * HWX;
  const int tid = threadIdx.x;

  for (int idx = tid; idx < 2048; idx += 256) {
    int plane = idx >> 10, rem = idx & 1023;
    int h = rem >> 4, g = rem & 15;
    const __nv_bfloat16* s = (plane ? srcL : srcH) + base + (size_t)(h0 + h) * WD + w0 + g * 4;
    *(uint2*)&tile[plane][h][g * 4] = *(const uint2*)s;
  }
  __syncthreads();
  for (int idx = tid; idx < 2048; idx += 256) {
    int plane = idx >> 10, rem = idx & 1023;
    int w = rem >> 4, g = rem & 15;
    __nv_bfloat16 v[4];
#pragma unroll
    for (int j = 0; j < 4; j++) v[j] = tile[plane][g * 4 + j][w];
    __nv_bfloat16* d = (plane ? dstL : dstH) + base + (size_t)(w0 + w) * WD + h0 + g * 4;
    *(uint2*)d = *(uint2*)v;
  }
}

// ---------------------------------------------------------------------------
extern "C" void kernel_launch(void* const* d_in, const int* in_sizes, int n_in,
                              void* d_out, int out_size)
{
  (void)in_sizes; (void)n_in; (void)out_size;
  const float* mainx  = (const float*)d_in[0];
  const float* assist = (const float*)d_in[1];
  const float* wq = (const float*)d_in[2];
  const float* bq = (const float*)d_in[3];
  const float* wk = (const float*)d_in[4];
  const float* bk = (const float*)d_in[5];
  const float* wv = (const float*)d_in[6];
  const float* bv = (const float*)d_in[7];
  float* out = (float*)d_out;

  __nv_bfloat16 *qh, *ql, *vh, *vl, *kh, *kl, *qth, *qtl, *vth, *vtl, *kth, *ktl;
  cudaGetSymbolAddress((void**)&qh,  g_qh);  cudaGetSymbolAddress((void**)&ql,  g_ql);
  cudaGetSymbolAddress((void**)&vh,  g_vh);  cudaGetSymbolAddress((void**)&vl,  g_vl);
  cudaGetSymbolAddress((void**)&kh,  g_kh);  cudaGetSymbolAddress((void**)&kl,  g_kl);
  cudaGetSymbolAddress((void**)&qth, g_qth); cudaGetSymbolAddress((void**)&qtl, g_qtl);
  cudaGetSymbolAddress((void**)&vth, g_vth); cudaGetSymbolAddress((void**)&vtl, g_vtl);
  cudaGetSymbolAddress((void**)&kth, g_kth); cudaGetSymbolAddress((void**)&ktl, g_ktl);

  cudaFuncSetAttribute(conv1x1_kernel<true>,  cudaFuncAttributeMaxDynamicSharedMemorySize, 49152);
  cudaFuncSetAttribute(conv1x1_kernel<false>, cudaFuncAttributeMaxDynamicSharedMemorySize, 32768);
  cudaFuncSetAttribute(time_fused_kernel,  cudaFuncAttributeMaxDynamicSharedMemorySize, SM_TOTAL);
  cudaFuncSetAttribute(space_score_kernel, cudaFuncAttributeMaxDynamicSharedMemorySize, SM_TOTAL);
  cudaFuncSetAttribute(space_ctx_kernel,   cudaFuncAttributeMaxDynamicSharedMemorySize, SM_TOTAL);

  // convs (bf16 hi/lo outputs)
  conv1x1_kernel<true><<<dim3(1024, 4), 256, 49152>>>(mainx, wq, bq, qh, ql, wv, bv, vh, vl);
  conv1x1_kernel<false><<<dim3(1024, 16), 256, 32768>>>(assist, wk, bk, kh, kl,
                                                        (const float*)0, (const float*)0,
                                                        (__nv_bfloat16*)0, (__nv_bfloat16*)0);
  // transposes
  transpose_kernel<<<dim3(256, 16), 256>>>(qh, ql, qth, qtl);
  transpose_kernel<<<dim3(256, 16), 256>>>(vh, vl, vth, vtl);
  transpose_kernel<<<dim3(1024, 16), 256>>>(kh, kl, kth, ktl);
  // attention
  time_fused_kernel<<<dim3(256, 4), 256, SM_TOTAL>>>(mainx, out);
  space_score_kernel<<<dim3(256, 4), 256, SM_TOTAL>>>();
  space_ctx_kernel<<<dim3(256, 4), 256, SM_TOTAL>>>(out);
}